// round 14
// baseline (speedup 1.0000x reference)
#include <cuda_runtime.h>

// Problem constants
#define Bq      128
#define Tq      1024
#define IN_DIM  17
#define Hq      512
#define OUT_DIM 17

// Partition: L0 blocks own NU0=12 units (G=48 cols, K=512+17),
//            L1 blocks own NU1=6 units (G=24 cols, K=1024, split-K warps).
#define NU0  12
#define NU1  6
#define NB0  43
#define NB1  86
#define NBLK (NB0 + NB1)      // 129 blocks <= 148 SMs, all co-resident

#define KC       64           // K-chunk rows (row = 128 f32 = 512B)
#define THREADS  544          // 16 compute warps + warp 16 (DMA lane 0)

// smem layout (bytes):
//   [0, 65536)       Hbuf[2][KC*128] f32   (epilogue gate buffer reuses Hbuf[0])
//   [65536, 65552)   mbar[2]
//   [65600, 114752)  Wbuf[2][KC*48] u64 (pre-duplicated f32x2 weights)
#define HS_BYTES       (2*KC*Bq*4)          // 65536
#define SMEM_MBAR_OFF  HS_BYTES
#define SMEM_WS_OFF    (HS_BYTES + 64)      // 65600, 16B aligned
#define WS_BYTES       (2*KC*48*8)          // 49152
#define SMEM_BYTES     (SMEM_WS_OFF + WS_BYTES)   // 114752

typedef unsigned long long u64;

// ---------------- persistent device state ----------------
__device__ __align__(128) float g_h0[2][Hq * Bq];
__device__ __align__(128) float g_h1[2][Hq * Bq];
__device__ __align__(128) float g_c0[Hq * Bq];
__device__ __align__(128) float g_c1[Hq * Bq];
__device__ __align__(128) float g_xT[Tq][IN_DIM][Bq];   // x transposed [t][i][b]
__device__ float g_bias0[4 * Hq];                        // bih0+bhh0
__device__ float g_bias1[4 * Hq];

// Per-block contiguous, pre-duplicated f32x2 weight slices:
//   L0: [blk][k][c] c=0..47 (c = gate*12 + u), k row stride 48 u64
//   L1: [blk][k][c] c=0..23 (c = gate*6 + u),  k row stride 24 u64
__device__ __align__(16) u64 g_w0d[(size_t)NB0 * Hq * 48];
__device__ __align__(16) u64 g_wx0[(size_t)NB0 * IN_DIM * 48];
__device__ __align__(16) u64 g_w1i[(size_t)NB1 * Hq * 24];
__device__ __align__(16) u64 g_w1h[(size_t)NB1 * Hq * 24];

// Grid barrier (sense reversal)
__device__ unsigned g_bar_count = 0;
__device__ volatile unsigned g_bar_gen = 0;

__device__ __forceinline__ void grid_barrier() {
    __syncthreads();
    if (threadIdx.x == 0) {
        unsigned gen = g_bar_gen;
        __threadfence();
        if (atomicAdd(&g_bar_count, 1) == NBLK - 1) {
            g_bar_count = 0;
            __threadfence();
            g_bar_gen = gen + 1;
        } else {
            while (g_bar_gen == gen) __nanosleep(64);
        }
    }
    __syncthreads();
}

__device__ __forceinline__ void fma2(u64 &a, u64 x, u64 y) {
    asm("fma.rn.f32x2 %0, %1, %2, %0;" : "+l"(a) : "l"(x), "l"(y));
}
__device__ __forceinline__ u64 pack2(float w) {
    u64 r; asm("mov.b64 %0, {%1, %1};" : "=l"(r) : "f"(w)); return r;
}

// ---------------- mbarrier + bulk-copy primitives ----------------
__device__ __forceinline__ void mbar_init(unsigned mbar, unsigned count) {
    asm volatile("mbarrier.init.shared.b64 [%0], %1;" :: "r"(mbar), "r"(count) : "memory");
}
__device__ __forceinline__ void mbar_expect(unsigned mbar, unsigned bytes) {
    asm volatile("mbarrier.arrive.expect_tx.shared.b64 _, [%0], %1;"
                 :: "r"(mbar), "r"(bytes) : "memory");
}
__device__ __forceinline__ void bulk_g2s(unsigned dst, const void* src,
                                         unsigned bytes, unsigned mbar) {
    asm volatile("cp.async.bulk.shared::cta.global.mbarrier::complete_tx::bytes "
                 "[%0], [%1], %2, [%3];"
                 :: "r"(dst), "l"(src), "r"(bytes), "r"(mbar) : "memory");
}
__device__ __forceinline__ void mbar_wait(unsigned mbar, unsigned phase) {
    asm volatile(
        "{\n\t.reg .pred P;\n\t"
        "WAIT_%=:\n\t"
        "mbarrier.try_wait.parity.acquire.cta.shared::cta.b64 P, [%0], %1, 0x989680;\n\t"
        "@P bra DONE_%=;\n\t"
        "bra WAIT_%=;\n\t"
        "DONE_%=:\n\t}"
        :: "r"(mbar), "r"(phase) : "memory");
}

// DMA: one chunk = H rows + matching duplicated-W rows on one mbarrier.
template<int GW>
__device__ __forceinline__ void dma_chunk(unsigned hs32, unsigned ws32,
                                          const float* Hg, const u64* Wg,
                                          int c, int kc, unsigned mb) {
    unsigned hb = (unsigned)kc * Bq * 4;
    unsigned wb = (unsigned)kc * GW * 8;
    mbar_expect(mb, hb + wb);
    bulk_g2s(hs32 + (unsigned)(c & 1) * KC * Bq * 4, Hg + (size_t)c * KC * Bq, hb, mb);
    bulk_g2s(ws32 + (unsigned)(c & 1) * KC * GW * 8, Wg + (size_t)c * KC * GW, wb, mb);
}

// ---------------- L0 GEMM: G=48, 16 warps, lane tile 4b x 3c ----------------
__device__ __forceinline__ void gemm_L0(const float* __restrict__ Hg,
                                        const u64* __restrict__ Wg, int K,
                                        u64 (&acc)[3][2],
                                        float* smemf, unsigned smem32,
                                        unsigned mb0, unsigned mb1,
                                        int &ph0, int &ph1)
{
    const int tid = threadIdx.x, lane = tid & 31, wid = tid >> 5;
    const int wr = wid & 3, cg = wid >> 2;          // batch quarter, col group
    const int gb = lane & 7, gc = lane >> 3;        // 4-batch group, 3-col group
    const bool dma = (tid == 512);
    const bool comp = (wid < 16);
    const float* Hs = smemf;
    const u64*   Ws = (const u64*)((const char*)smemf + SMEM_WS_OFF);
    const unsigned hs32 = smem32, ws32 = smem32 + SMEM_WS_OFF;
    const int nch = (K + KC - 1) / KC;

    if (dma) {
        int kc0 = K < KC ? K : KC;
        dma_chunk<48>(hs32, ws32, Hg, Wg, 0, kc0, mb0);
        if (nch > 1) {
            int kc1 = K - KC < KC ? K - KC : KC;
            dma_chunk<48>(hs32, ws32, Hg, Wg, 1, kc1, mb1);
        }
    }
    for (int c = 0; c < nch; ++c) {
        int kc = K - c * KC; if (kc > KC) kc = KC;
        if (comp) {
            if (c & 1) { mbar_wait(mb1, ph1); ph1 ^= 1; }
            else       { mbar_wait(mb0, ph0); ph0 ^= 1; }
            const float* hp = Hs + (c & 1) * KC * Bq + wr * 32 + gb * 4;
            const u64*   wp = Ws + (c & 1) * KC * 48 + cg * 12 + gc * 3;
            if (kc == KC) {
                #pragma unroll 8
                for (int k = 0; k < KC; ++k) {
                    ulonglong2 h = *(const ulonglong2*)(hp + k * Bq);
                    u64 w0 = wp[k * 48], w1 = wp[k * 48 + 1], w2 = wp[k * 48 + 2];
                    fma2(acc[0][0], h.x, w0); fma2(acc[0][1], h.y, w0);
                    fma2(acc[1][0], h.x, w1); fma2(acc[1][1], h.y, w1);
                    fma2(acc[2][0], h.x, w2); fma2(acc[2][1], h.y, w2);
                }
            } else {
                for (int k = 0; k < kc; ++k) {
                    ulonglong2 h = *(const ulonglong2*)(hp + k * Bq);
                    u64 w0 = wp[k * 48], w1 = wp[k * 48 + 1], w2 = wp[k * 48 + 2];
                    fma2(acc[0][0], h.x, w0); fma2(acc[0][1], h.y, w0);
                    fma2(acc[1][0], h.x, w1); fma2(acc[1][1], h.y, w1);
                    fma2(acc[2][0], h.x, w2); fma2(acc[2][1], h.y, w2);
                }
            }
        } else {
            if (c & 1) { mbar_wait(mb1, ph1); ph1 ^= 1; }
            else       { mbar_wait(mb0, ph0); ph0 ^= 1; }
        }
        __syncthreads();
        if (dma && c + 2 < nch) {
            int kc2 = K - (c + 2) * KC; if (kc2 > KC) kc2 = KC;
            dma_chunk<48>(hs32, ws32, Hg, Wg, c + 2, kc2, (c & 1) ? mb1 : mb0);
        }
    }
}

// ---------------- L1 GEMM: G=24, split-K warp halves, lane tile 2b x 6c ------
// K must be 512 (8 full chunks). Warps 0..7: k 0..31 of chunk; 8..15: k 32..63.
__device__ __forceinline__ void gemm_L1(const float* __restrict__ Hg,
                                        const u64* __restrict__ Wg,
                                        u64 (&acc)[6],
                                        float* smemf, unsigned smem32,
                                        unsigned mb0, unsigned mb1,
                                        int &ph0, int &ph1)
{
    const int tid = threadIdx.x, lane = tid & 31, wid = tid >> 5;
    const int w8 = wid & 7, kh = (wid >> 3) & 1;
    const int bq = w8 & 3, cgw = w8 >> 2;           // batch quarter, col group
    const int gb = lane & 15, gc = lane >> 4;       // 2-batch group, 6-col group
    const bool dma = (tid == 512);
    const bool comp = (wid < 16);
    const float* Hs = smemf;
    const u64*   Ws = (const u64*)((const char*)smemf + SMEM_WS_OFF);
    const unsigned hs32 = smem32, ws32 = smem32 + SMEM_WS_OFF;
    const int nch = Hq / KC;                        // 8

    if (dma) {
        dma_chunk<24>(hs32, ws32, Hg, Wg, 0, KC, mb0);
        dma_chunk<24>(hs32, ws32, Hg, Wg, 1, KC, mb1);
    }
    for (int c = 0; c < nch; ++c) {
        if (c & 1) { mbar_wait(mb1, ph1); ph1 ^= 1; }
        else       { mbar_wait(mb0, ph0); ph0 ^= 1; }
        if (comp) {
            const float* hp = Hs + (c & 1) * KC * Bq + kh * 32 * Bq + bq * 32 + gb * 2;
            const u64*   wp = Ws + (c & 1) * KC * 24 + kh * 32 * 24 + cgw * 12 + gc * 6;
            #pragma unroll 8
            for (int k = 0; k < 32; ++k) {
                u64 h = *(const u64*)(hp + k * Bq);
                ulonglong2 wA = *(const ulonglong2*)(wp + k * 24);
                ulonglong2 wB = *(const ulonglong2*)(wp + k * 24 + 2);
                ulonglong2 wC = *(const ulonglong2*)(wp + k * 24 + 4);
                fma2(acc[0], h, wA.x); fma2(acc[1], h, wA.y);
                fma2(acc[2], h, wB.x); fma2(acc[3], h, wB.y);
                fma2(acc[4], h, wC.x); fma2(acc[5], h, wC.y);
            }
        }
        __syncthreads();
        if (dma && c + 2 < nch)
            dma_chunk<24>(hs32, ws32, Hg, Wg, c + 2, KC, (c & 1) ? mb1 : mb0);
    }
}

// ---------------- LSTM cell math ----------------
__device__ __forceinline__ void cell(float gi, float gf, float gg, float go,
                                     float* __restrict__ cbuf,
                                     float* __restrict__ hdst, int off)
{
    float ig = 1.f / (1.f + __expf(-gi));
    float fg = 1.f / (1.f + __expf(-gf));
    float og = 1.f / (1.f + __expf(-go));
    float gv = tanhf(gg);
    float cn = fg * cbuf[off] + ig * gv;
    cbuf[off] = cn;
    __stcg(&hdst[off], og * tanhf(cn));
}

// ---------------- epilogues ----------------
__device__ __forceinline__ void epilogue_L0(int u0, u64 (&acc)[3][2],
                                            const float* __restrict__ bias,
                                            float* __restrict__ cbuf,
                                            float* __restrict__ hdst, float* smemf)
{
    const int tid = threadIdx.x, lane = tid & 31, wid = tid >> 5;
    const int wr = wid & 3, cg = wid >> 2;
    const int gb = lane & 7, gc = lane >> 3;
    ulonglong2* Gs2 = (ulonglong2*)smemf;           // [c][32] u2 = [c][128] f32
    if (wid < 16) {
        #pragma unroll
        for (int j = 0; j < 3; ++j) {
            int c = cg * 12 + gc * 3 + j;
            Gs2[c * 32 + wr * 8 + gb] = make_ulonglong2(acc[j][0], acc[j][1]);
        }
    }
    __syncthreads();
    if (tid < 512) {
        const float* Gf = smemf;
        const int b = tid & 127, q = tid >> 7;
        #pragma unroll
        for (int u = q; u < NU0; u += 4) {
            int unit = u0 + u;
            if (unit < Hq) {
                float gi = Gf[(u           ) * Bq + b] + bias[unit         ];
                float gf = Gf[(u +     NU0) * Bq + b] + bias[unit +     Hq];
                float gg = Gf[(u + 2 * NU0) * Bq + b] + bias[unit + 2 * Hq];
                float go = Gf[(u + 3 * NU0) * Bq + b] + bias[unit + 3 * Hq];
                cell(gi, gf, gg, go, cbuf, hdst, unit * Bq + b);
            }
        }
    }
    __syncthreads();
}

__device__ __forceinline__ void epilogue_L1(int u0, u64 (&acc)[6],
                                            const float* __restrict__ bias,
                                            float* __restrict__ cbuf,
                                            float* __restrict__ hdst, float* smemf)
{
    const int tid = threadIdx.x, lane = tid & 31, wid = tid >> 5;
    const int w8 = wid & 7, kh = (wid >> 3) & 1;
    const int bq = w8 & 3, cgw = w8 >> 2;
    const int gb = lane & 15, gc = lane >> 4;
    u64* Gs = (u64*)smemf;                          // [kh][c][64] u64
    if (wid < 16) {
        #pragma unroll
        for (int j = 0; j < 6; ++j) {
            int c = cgw * 12 + gc * 6 + j;
            Gs[kh * (24 * 64) + c * 64 + bq * 16 + gb] = acc[j];
        }
    }
    __syncthreads();
    if (tid < 512) {
        const float* Gf = smemf;
        const float* Gf2 = smemf + 24 * Bq;
        const int b = tid & 127, q = tid >> 7;
        #pragma unroll
        for (int u = q; u < NU1; u += 4) {
            int unit = u0 + u;
            if (unit < Hq) {
                float gi = Gf[(u           ) * Bq + b] + Gf2[(u           ) * Bq + b] + bias[unit         ];
                float gf = Gf[(u +     NU1) * Bq + b] + Gf2[(u +     NU1) * Bq + b] + bias[unit +     Hq];
                float gg = Gf[(u + 2 * NU1) * Bq + b] + Gf2[(u + 2 * NU1) * Bq + b] + bias[unit + 2 * Hq];
                float go = Gf[(u + 3 * NU1) * Bq + b] + Gf2[(u + 3 * NU1) * Bq + b] + bias[unit + 3 * Hq];
                cell(gi, gf, gg, go, cbuf, hdst, unit * Bq + b);
            }
        }
    }
    __syncthreads();
}

// ---------------- persistent kernel ----------------
__global__ void __launch_bounds__(THREADS, 1)
lstm_persistent(const float* __restrict__ x,
                const float* __restrict__ wih0, const float* __restrict__ whh0,
                const float* __restrict__ bih0, const float* __restrict__ bhh0,
                const float* __restrict__ wih1, const float* __restrict__ whh1,
                const float* __restrict__ bih1, const float* __restrict__ bhh1,
                const float* __restrict__ lin_w, const float* __restrict__ lin_b,
                float* __restrict__ out)
{
    extern __shared__ float smemf[];
    const unsigned smem32 = (unsigned)__cvta_generic_to_shared(smemf);
    const unsigned mb0 = smem32 + SMEM_MBAR_OFF, mb1 = mb0 + 8;
    const int blk = blockIdx.x, tid = threadIdx.x;

    // ---- one-time init: states, biases, x transpose (grid-distributed) ----
    {
        const int gi = blk * THREADS + tid, gs = NBLK * THREADS;
        for (int i = gi; i < 2 * Hq * Bq; i += gs) {
            ((float*)g_h0)[i] = 0.f;  ((float*)g_h1)[i] = 0.f;
        }
        for (int i = gi; i < Hq * Bq; i += gs) { g_c0[i] = 0.f; g_c1[i] = 0.f; }
        for (int g = gi; g < 4 * Hq; g += gs) {
            g_bias0[g] = bih0[g] + bhh0[g];
            g_bias1[g] = bih1[g] + bhh1[g];
        }
        const int NX = Bq * Tq * IN_DIM;
        for (int i = gi; i < NX; i += gs) {
            int b = i / (Tq * IN_DIM);
            int r = i - b * (Tq * IN_DIM);
            int t = r / IN_DIM, ii = r - t * IN_DIM;
            g_xT[t][ii][b] = x[i];
        }
    }
    // ---- per-block duplicated-weight gather into contiguous global slices ----
    if (blk < NB0) {
        const int u0 = blk * NU0;
        u64* wd = g_w0d + (size_t)blk * Hq * 48;
        for (int i = tid; i < Hq * 48; i += THREADS) {
            int k = i / 48, c = i - (i / 48) * 48;
            int gate = c / 12, u = c - gate * 12;
            int unit = u0 + u; if (unit > Hq - 1) unit = Hq - 1;
            wd[i] = pack2(whh0[(size_t)(gate * Hq + unit) * Hq + k]);
        }
        u64* wx = g_wx0 + (size_t)blk * IN_DIM * 48;
        for (int i = tid; i < IN_DIM * 48; i += THREADS) {
            int k = i / 48, c = i - (i / 48) * 48;
            int gate = c / 12, u = c - gate * 12;
            int unit = u0 + u; if (unit > Hq - 1) unit = Hq - 1;
            wx[i] = pack2(wih0[(size_t)(gate * Hq + unit) * IN_DIM + k]);
        }
    } else {
        const int lb = blk - NB0, u0 = lb * NU1;
        u64* wi = g_w1i + (size_t)lb * Hq * 24;
        u64* wh = g_w1h + (size_t)lb * Hq * 24;
        for (int i = tid; i < Hq * 24; i += THREADS) {
            int k = i / 24, c = i - (i / 24) * 24;
            int gate = c / 6, u = c - gate * 6;
            int unit = u0 + u; if (unit > Hq - 1) unit = Hq - 1;
            wi[i] = pack2(wih1[(size_t)(gate * Hq + unit) * Hq + k]);
            wh[i] = pack2(whh1[(size_t)(gate * Hq + unit) * Hq + k]);
        }
    }
    if (tid == 0) { mbar_init(mb0, 1); mbar_init(mb1, 1); }
    __syncthreads();
    grid_barrier();   // includes threadfence: gathers visible to TMA everywhere

    int ph0 = 0, ph1 = 0;

    // ---- pipelined recurrence: L0 step t || L1 step t-1 ----
    if (blk < NB0) {
        const int u0 = blk * NU0;
        const u64* wd = g_w0d + (size_t)blk * Hq * 48;
        const u64* wx = g_wx0 + (size_t)blk * IN_DIM * 48;
        #pragma unroll 1
        for (int t = 0; t <= Tq; ++t) {
            if (t < Tq) {
                u64 acc[3][2];
                #pragma unroll
                for (int j = 0; j < 3; ++j) { acc[j][0] = 0ull; acc[j][1] = 0ull; }
                gemm_L0(g_h0[(t + 1) & 1], wd, Hq, acc, smemf, smem32, mb0, mb1, ph0, ph1);
                gemm_L0(&g_xT[t][0][0], wx, IN_DIM, acc, smemf, smem32, mb0, mb1, ph0, ph1);
                epilogue_L0(u0, acc, g_bias0, g_c0, g_h0[t & 1], smemf);
            }
            grid_barrier();
        }
    } else {
        const int lb = blk - NB0, u0 = lb * NU1;
        const u64* wi = g_w1i + (size_t)lb * Hq * 24;
        const u64* wh = g_w1h + (size_t)lb * Hq * 24;
        #pragma unroll 1
        for (int t = 0; t <= Tq; ++t) {
            if (t >= 1) {
                const int s = t - 1;
                u64 acc[6];
                #pragma unroll
                for (int j = 0; j < 6; ++j) acc[j] = 0ull;
                gemm_L1(g_h0[s & 1],       wi, acc, smemf, smem32, mb0, mb1, ph0, ph1);
                gemm_L1(g_h1[(s + 1) & 1], wh, acc, smemf, smem32, mb0, mb1, ph0, ph1);
                epilogue_L1(u0, acc, g_bias1, g_c1, g_h1[s & 1], smemf);
            }
            grid_barrier();
        }
    }

    // ---- final linear: out[b][o] = h1_last[:,b] . lin_w[o,:] + lin_b[o] ----
    if (blk < OUT_DIM && tid < Bq) {
        const int o = blk, b = tid;
        const float* h = g_h1[(Tq - 1) & 1];
        float a = __ldg(&lin_b[o]);
        #pragma unroll 8
        for (int k = 0; k < Hq; ++k)
            a += __ldcg(&h[k * Bq + b]) * __ldg(&lin_w[o * Hq + k]);
        out[b * OUT_DIM + o] = a;
    }
}

extern "C" void kernel_launch(void* const* d_in, const int* in_sizes, int n_in,
                              void* d_out, int out_size)
{
    const float* x     = (const float*)d_in[0];
    const float* wih0  = (const float*)d_in[1];
    const float* whh0  = (const float*)d_in[2];
    const float* bih0  = (const float*)d_in[3];
    const float* bhh0  = (const float*)d_in[4];
    const float* wih1  = (const float*)d_in[5];
    const float* whh1  = (const float*)d_in[6];
    const float* bih1  = (const float*)d_in[7];
    const float* bhh1  = (const float*)d_in[8];
    const float* lin_w = (const float*)d_in[9];
    const float* lin_b = (const float*)d_in[10];
    float* out = (float*)d_out;

    cudaFuncSetAttribute(lstm_persistent,
                         cudaFuncAttributeMaxDynamicSharedMemorySize, SMEM_BYTES);

    lstm_persistent<<<NBLK, THREADS, SMEM_BYTES>>>(
        x, wih0, whh0, bih0, bhh0, wih1, whh1, bih1, bhh1, lin_w, lin_b, out);
}